// round 16
// baseline (speedup 1.0000x reference)
#include <cuda_runtime.h>
#include <cuda_fp16.h>
#include <cstdint>

// Problem constants (fixed by the reference).
#define D_IN_   2048
#define D_SAE_  32768
#define N_      8192
#define K_      64

// Gather tiling (R3/R11-proven): CD dims per chunk (fp16 footprint 32MB,
// L2-resident), RN rows per CTA.
#define CD      512
#define RN      16

// Scratch (device globals — no allocation allowed in kernel_launch).
__device__ __half g_Wth[(size_t)D_SAE_ * D_IN_];  // transposed W fp16 (D_SAE, D_IN)
__device__ float  g_vals[N_ * K_];                // deduped values

// ---------------------------------------------------------------------------
// Kernel 1 (fused, EXACT R13 — measured best, no __ldcs): transpose+convert
// W_dec (D_IN, D_SAE) fp32 -> g_Wth (D_SAE, D_IN) fp16, AND dedupe values
// (folded into the first 2048 blocks).
// Tile 32 s x 128 d, tile[32][129], MLP=4 reads (the measured optimum of the
// MLP dial: 2->4 gained, 4->8 regressed), measured-good write phase.
// ---------------------------------------------------------------------------
__global__ __launch_bounds__(256)
void transpose_dedupe_kernel(const float* __restrict__ W,
                             const int*   __restrict__ idx,
                             const float* __restrict__ vals) {
    __shared__ float tile[32][129];  // [s_local][d_local]

    int t  = threadIdx.x;            // 0..255
    int tx = t & 31;
    int ty = t >> 5;                 // 0..7
    int s0 = blockIdx.x * 32;
    int d0 = blockIdx.y * 128;

    // ---- read phase: 128 d-rows x 8 float4 = 1024 tasks, 4 per thread ----
    #pragma unroll
    for (int i = 0; i < 4; ++i) {
        int e  = i * 256 + t;
        int dl = e >> 3;             // d_local 0..127
        int s4 = (e & 7) * 4;        // s_local, float4 granularity
        float4 v = *reinterpret_cast<const float4*>(
            W + (size_t)(d0 + dl) * D_SAE_ + s0 + s4);
        tile[s4 + 0][dl] = v.x;
        tile[s4 + 1][dl] = v.y;
        tile[s4 + 2][dl] = v.z;
        tile[s4 + 3][dl] = v.w;
    }
    __syncthreads();

    // ---- write phase: 32 s-rows x 128 d = 2048 half2 tasks, 8 per thread --
    #pragma unroll
    for (int j = 0; j < 8; ++j) {
        int s_local = ty + 8 * (j & 3);
        int d_local = tx * 2 + 64 * (j >> 2);
        __half2 h = __floats2half2_rn(tile[s_local][d_local],
                                      tile[s_local][d_local + 1]);
        *reinterpret_cast<__half2*>(
            &g_Wth[(size_t)(s0 + s_local) * D_IN_ + d0 + d_local]) = h;
    }

    // ---- dedupe (first 2048 blocks; 4 rows each). Reference scatter is
    // .set(): LAST duplicate wins -> zero values whose index reappears later.
    int bid = blockIdx.y * gridDim.x + blockIdx.x;
    if (bid < N_ / 4) {
        __shared__ int sidx[4][K_];
        int lr  = t >> 6;
        int k   = t & 63;
        int row = bid * 4 + lr;
        int sv  = idx[row * K_ + k];
        sidx[lr][k] = sv;
        __syncthreads();
        bool keep = true;
        #pragma unroll 1
        for (int k2 = k + 1; k2 < K_; ++k2)
            if (sidx[lr][k2] == sv) keep = false;
        g_vals[row * K_ + k] = keep ? vals[row * K_ + k] : 0.0f;
    }
}

// ---------------------------------------------------------------------------
// Kernel 2: gather-FMA — R13 in every respect EXCEPT the W load: each
// 16B LDG.128 is split into two independent 8B LDG.64s.
// Hypothesis under test: the gather's 126us floor is L1tex wavefront REPLAY
// (LDG.128/warp = 8 wavefronts at ~2.07cyc within-LDG; LDG.64/warp = 2
// wavefronts at ~1.5cyc avg). Same bytes, same MLP region, +1 issue slot/k
// (issue was 60% — headroom).
// ---------------------------------------------------------------------------
__global__ __launch_bounds__(256)
void gather_kernel(const int* __restrict__ idx,
                   const float* __restrict__ b_dec,
                   float* __restrict__ out) {
    __shared__ int   soff[RN][K_];
    __shared__ float sval[RN][K_];

    int r0  = blockIdx.x * RN;
    int d0  = blockIdx.y * CD;
    int tid = threadIdx.x;

    #pragma unroll
    for (int i = tid; i < RN * K_; i += 256) {
        soff[0][i] = idx[r0 * K_ + i] * D_IN_;
        sval[0][i] = g_vals[r0 * K_ + i];
    }
    __syncthreads();

    int td = tid & 63;            // dim-thread
    int tr = tid >> 6;            // row group 0..3
    int d  = d0 + td * 8;         // 8 contiguous dims per thread

    float bb[8];
    {
        float4 b0 = *reinterpret_cast<const float4*>(b_dec + d);
        float4 b1 = *reinterpret_cast<const float4*>(b_dec + d + 4);
        bb[0] = b0.x; bb[1] = b0.y; bb[2] = b0.z; bb[3] = b0.w;
        bb[4] = b1.x; bb[5] = b1.y; bb[6] = b1.z; bb[7] = b1.w;
    }

    const __half* Wt = g_Wth;

    #pragma unroll 1
    for (int i = 0; i < 4; ++i) {
        int r = tr * 4 + i;
        float acc[8];
        #pragma unroll
        for (int j = 0; j < 8; ++j) acc[j] = bb[j];

        #pragma unroll 8
        for (int k = 0; k < K_; ++k) {
            int   off = soff[r][k] + d;
            float v   = sval[r][k];
            // Two independent LDG.64s instead of one LDG.128.
            uint2 wa = *reinterpret_cast<const uint2*>(Wt + off);
            uint2 wb = *reinterpret_cast<const uint2*>(Wt + off + 4);
            __half2 h0 = *reinterpret_cast<__half2*>(&wa.x);
            __half2 h1 = *reinterpret_cast<__half2*>(&wa.y);
            __half2 h2 = *reinterpret_cast<__half2*>(&wb.x);
            __half2 h3 = *reinterpret_cast<__half2*>(&wb.y);
            float2 f0 = __half22float2(h0);
            float2 f1 = __half22float2(h1);
            float2 f2 = __half22float2(h2);
            float2 f3 = __half22float2(h3);
            acc[0] = fmaf(v, f0.x, acc[0]);
            acc[1] = fmaf(v, f0.y, acc[1]);
            acc[2] = fmaf(v, f1.x, acc[2]);
            acc[3] = fmaf(v, f1.y, acc[3]);
            acc[4] = fmaf(v, f2.x, acc[4]);
            acc[5] = fmaf(v, f2.y, acc[5]);
            acc[6] = fmaf(v, f3.x, acc[6]);
            acc[7] = fmaf(v, f3.y, acc[7]);
        }

        float* orow = out + (size_t)(r0 + r) * D_IN_ + d;
        // Streaming stores: don't let the 64MB output evict the W chunk in L2.
        __stcs(reinterpret_cast<float4*>(orow),
               make_float4(acc[0], acc[1], acc[2], acc[3]));
        __stcs(reinterpret_cast<float4*>(orow + 4),
               make_float4(acc[4], acc[5], acc[6], acc[7]));
    }
}

// ---------------------------------------------------------------------------
// Launch. Inputs (metadata order): indices(int32 N*K), values(f32 N*K),
// W_dec(f32 D_IN*D_SAE), b_dec(f32 D_IN). Output: f32 N*D_IN.
// Graph-capturable: 2 plain kernel launches, zero allocation, zero sync.
// ---------------------------------------------------------------------------
extern "C" void kernel_launch(void* const* d_in, const int* in_sizes, int n_in,
                              void* d_out, int out_size) {
    const int*   indices = (const int*)  d_in[0];
    const float* values  = (const float*)d_in[1];
    const float* W       = (const float*)d_in[2];
    const float* b       = (const float*)d_in[3];
    float*       out     = (float*)d_out;

    dim3 tg(D_SAE_ / 32, D_IN_ / 128);
    transpose_dedupe_kernel<<<tg, 256>>>(W, indices, values);

    dim3 gg(N_ / RN, D_IN_ / CD);   // x = row tiles (fast), y = d-chunks (slow)
    gather_kernel<<<gg, 256>>>(indices, b, out);
}

// round 17
// speedup vs baseline: 1.1869x; 1.1869x over previous
#include <cuda_runtime.h>
#include <cuda_fp16.h>
#include <cstdint>

// Problem constants (fixed by the reference).
#define D_IN_   2048
#define D_SAE_  32768
#define N_      8192
#define K_      64

// Gather tiling (R3/R11/R13-proven): CD dims per chunk (fp16 footprint 32MB,
// L2-resident), RN rows per CTA.
#define CD      512
#define RN      16

// Scratch (device globals — no allocation allowed in kernel_launch).
__device__ __half g_Wth[(size_t)D_SAE_ * D_IN_];  // transposed W fp16 (D_SAE, D_IN)
__device__ float  g_vals[N_ * K_];                // deduped values

// ---------------------------------------------------------------------------
// Kernel 1 (fused, EXACT R13 — the measured best over 16 rounds):
// transpose+convert W_dec (D_IN, D_SAE) fp32 -> g_Wth (D_SAE, D_IN) fp16,
// AND dedupe values (folded into the first 2048 blocks).
//
// Tile 32 s x 128 d, tile[32][129] (16.5KB smem):
//   read : 4x LDG.128/thread per barrier. MLP=4 is the measured optimum of
//          the MLP dial (2->4: +6us; 4->8: -102us). Plain loads (__ldcs
//          measured -1.7us in R15). STS banks (s4+j+dl) mod 32 all distinct
//          within a warp (129 = 1 mod 32, verified arithmetic).
//   write: 8x (scalar LDS pair + __half2 STG), 128B/warp (measured good;
//          wide smem write phases hit alignment/bank traps in R8/R10).
// ---------------------------------------------------------------------------
__global__ __launch_bounds__(256)
void transpose_dedupe_kernel(const float* __restrict__ W,
                             const int*   __restrict__ idx,
                             const float* __restrict__ vals) {
    __shared__ float tile[32][129];  // [s_local][d_local]

    int t  = threadIdx.x;            // 0..255
    int tx = t & 31;
    int ty = t >> 5;                 // 0..7
    int s0 = blockIdx.x * 32;
    int d0 = blockIdx.y * 128;

    // ---- read phase: 128 d-rows x 8 float4 = 1024 tasks, 4 per thread ----
    #pragma unroll
    for (int i = 0; i < 4; ++i) {
        int e  = i * 256 + t;
        int dl = e >> 3;             // d_local 0..127
        int s4 = (e & 7) * 4;        // s_local, float4 granularity
        float4 v = *reinterpret_cast<const float4*>(
            W + (size_t)(d0 + dl) * D_SAE_ + s0 + s4);
        tile[s4 + 0][dl] = v.x;
        tile[s4 + 1][dl] = v.y;
        tile[s4 + 2][dl] = v.z;
        tile[s4 + 3][dl] = v.w;
    }
    __syncthreads();

    // ---- write phase: 32 s-rows x 128 d = 2048 half2 tasks, 8 per thread --
    #pragma unroll
    for (int j = 0; j < 8; ++j) {
        int s_local = ty + 8 * (j & 3);
        int d_local = tx * 2 + 64 * (j >> 2);
        __half2 h = __floats2half2_rn(tile[s_local][d_local],
                                      tile[s_local][d_local + 1]);
        *reinterpret_cast<__half2*>(
            &g_Wth[(size_t)(s0 + s_local) * D_IN_ + d0 + d_local]) = h;
    }

    // ---- dedupe (first 2048 blocks; 4 rows each). Reference scatter is
    // .set(): LAST duplicate wins -> zero values whose index reappears later.
    int bid = blockIdx.y * gridDim.x + blockIdx.x;
    if (bid < N_ / 4) {
        __shared__ int sidx[4][K_];
        int lr  = t >> 6;
        int k   = t & 63;
        int row = bid * 4 + lr;
        int sv  = idx[row * K_ + k];
        sidx[lr][k] = sv;
        __syncthreads();
        bool keep = true;
        #pragma unroll 1
        for (int k2 = k + 1; k2 < K_; ++k2)
            if (sidx[lr][k2] == sv) keep = false;
        g_vals[row * K_ + k] = keep ? vals[row * K_ + k] : 0.0f;
    }
}

// ---------------------------------------------------------------------------
// Kernel 2: gather-FMA — EXACT R3/R11/R13 kernel and launch shape. Measured
// at the L1tex/L2 equilibrium (~126us, L2 71%, seven consistent profiles).
// Every neighborhood move measured worse: LDG.64 (R6/R16), reg squeeze (R4),
// HFMA2 (R5), persistence (R9), overlap (R7/R12). LDG.128, 8 dims/thread,
// fp32 FFMA, bias in regs, 2048-CTA wave-synchronized chunk sweep.
// ---------------------------------------------------------------------------
__global__ __launch_bounds__(256)
void gather_kernel(const int* __restrict__ idx,
                   const float* __restrict__ b_dec,
                   float* __restrict__ out) {
    __shared__ int   soff[RN][K_];
    __shared__ float sval[RN][K_];

    int r0  = blockIdx.x * RN;
    int d0  = blockIdx.y * CD;
    int tid = threadIdx.x;

    #pragma unroll
    for (int i = tid; i < RN * K_; i += 256) {
        soff[0][i] = idx[r0 * K_ + i] * D_IN_;
        sval[0][i] = g_vals[r0 * K_ + i];
    }
    __syncthreads();

    int td = tid & 63;            // dim-thread
    int tr = tid >> 6;            // row group 0..3
    int d  = d0 + td * 8;         // 8 contiguous dims (16B fp16) per thread

    float bb[8];
    {
        float4 b0 = *reinterpret_cast<const float4*>(b_dec + d);
        float4 b1 = *reinterpret_cast<const float4*>(b_dec + d + 4);
        bb[0] = b0.x; bb[1] = b0.y; bb[2] = b0.z; bb[3] = b0.w;
        bb[4] = b1.x; bb[5] = b1.y; bb[6] = b1.z; bb[7] = b1.w;
    }

    const __half* Wt = g_Wth;

    #pragma unroll 1
    for (int i = 0; i < 4; ++i) {
        int r = tr * 4 + i;
        float acc[8];
        #pragma unroll
        for (int j = 0; j < 8; ++j) acc[j] = bb[j];

        #pragma unroll 8
        for (int k = 0; k < K_; ++k) {
            int   off = soff[r][k] + d;
            float v   = sval[r][k];
            uint4 w   = *reinterpret_cast<const uint4*>(Wt + off);
            __half2 h0 = *reinterpret_cast<__half2*>(&w.x);
            __half2 h1 = *reinterpret_cast<__half2*>(&w.y);
            __half2 h2 = *reinterpret_cast<__half2*>(&w.z);
            __half2 h3 = *reinterpret_cast<__half2*>(&w.w);
            float2 f0 = __half22float2(h0);
            float2 f1 = __half22float2(h1);
            float2 f2 = __half22float2(h2);
            float2 f3 = __half22float2(h3);
            acc[0] = fmaf(v, f0.x, acc[0]);
            acc[1] = fmaf(v, f0.y, acc[1]);
            acc[2] = fmaf(v, f1.x, acc[2]);
            acc[3] = fmaf(v, f1.y, acc[3]);
            acc[4] = fmaf(v, f2.x, acc[4]);
            acc[5] = fmaf(v, f2.y, acc[5]);
            acc[6] = fmaf(v, f3.x, acc[6]);
            acc[7] = fmaf(v, f3.y, acc[7]);
        }

        float* orow = out + (size_t)(r0 + r) * D_IN_ + d;
        // Streaming stores: don't let the 64MB output evict the W chunk in L2.
        __stcs(reinterpret_cast<float4*>(orow),
               make_float4(acc[0], acc[1], acc[2], acc[3]));
        __stcs(reinterpret_cast<float4*>(orow + 4),
               make_float4(acc[4], acc[5], acc[6], acc[7]));
    }
}

// ---------------------------------------------------------------------------
// Launch. Inputs (metadata order): indices(int32 N*K), values(f32 N*K),
// W_dec(f32 D_IN*D_SAE), b_dec(f32 D_IN). Output: f32 N*D_IN.
// Graph-capturable: 2 plain kernel launches, zero allocation, zero sync.
// ---------------------------------------------------------------------------
extern "C" void kernel_launch(void* const* d_in, const int* in_sizes, int n_in,
                              void* d_out, int out_size) {
    const int*   indices = (const int*)  d_in[0];
    const float* values  = (const float*)d_in[1];
    const float* W       = (const float*)d_in[2];
    const float* b       = (const float*)d_in[3];
    float*       out     = (float*)d_out;

    dim3 tg(D_SAE_ / 32, D_IN_ / 128);
    transpose_dedupe_kernel<<<tg, 256>>>(W, indices, values);

    dim3 gg(N_ / RN, D_IN_ / CD);   // x = row tiles (fast), y = d-chunks (slow)
    gather_kernel<<<gg, 256>>>(indices, b, out);
}